// round 5
// baseline (speedup 1.0000x reference)
#include <cuda_runtime.h>
#include <cstdint>

// N-body all-pairs gravity, fp32, packed f32x2 math (retry of R2 with the
// R3 occupancy fix). The kernel is fma-pipe-rate bound (R3/R4 both sit at the
// 24 SMSP-cyc/warp-interaction FFMA wall); f32x2 halves fma-pipe slots per
// interaction. Tile is stored pre-paired so LDS.128 yields packed operands.

constexpr int NBODY  = 8192;
constexpr int BLOCK  = 256;
constexpr int NSPLIT = 32;                // grid 32 x 32 = 1024 CTAs
constexpr int CHUNK  = NBODY / NSPLIT;    // 256 j-bodies per tile
constexpr int PAIRS  = CHUNK / 2;         // 128 packed pairs (4 KB smem)

__device__ __forceinline__ uint64_t pk2(float lo, float hi) {
    uint64_t r; asm("mov.b64 %0, {%1, %2};" : "=l"(r) : "f"(lo), "f"(hi)); return r;
}
__device__ __forceinline__ void upk2(uint64_t v, float& lo, float& hi) {
    asm("mov.b64 {%0, %1}, %2;" : "=f"(lo), "=f"(hi) : "l"(v));
}
__device__ __forceinline__ uint64_t add2(uint64_t a, uint64_t b) {
    uint64_t r; asm("add.rn.f32x2 %0, %1, %2;" : "=l"(r) : "l"(a), "l"(b)); return r;
}
__device__ __forceinline__ uint64_t mul2(uint64_t a, uint64_t b) {
    uint64_t r; asm("mul.rn.f32x2 %0, %1, %2;" : "=l"(r) : "l"(a), "l"(b)); return r;
}
__device__ __forceinline__ uint64_t fma2(uint64_t a, uint64_t b, uint64_t c) {
    uint64_t r; asm("fma.rn.f32x2 %0, %1, %2, %3;" : "=l"(r) : "l"(a), "l"(b), "l"(c)); return r;
}

__global__ __launch_bounds__(BLOCK)
void nbody_kernel(const float* __restrict__ pos,
                  const float* __restrict__ mass,
                  float* __restrict__ out)
{
    // Pre-paired tile: shXY[p] = {x(j0), x(j1), y(j0), y(j1)},
    //                  shZM[p] = {z(j0), z(j1), m(j0), m(j1)}.
    __shared__ float4 shXY[PAIRS];
    __shared__ float4 shZM[PAIRS];

    const int i     = blockIdx.x * BLOCK + threadIdx.x;
    const int jBase = blockIdx.y * CHUNK;

    if (threadIdx.x < PAIRS) {
        const int p  = threadIdx.x;
        const int j0 = jBase + 2 * p;
        const int j1 = j0 + 1;
        shXY[p] = make_float4(pos[3 * j0 + 0], pos[3 * j1 + 0],
                              pos[3 * j0 + 1], pos[3 * j1 + 1]);
        shZM[p] = make_float4(pos[3 * j0 + 2], pos[3 * j1 + 2],
                              mass[j0],        mass[j1]);
    }
    __syncthreads();

    const float px = pos[3 * i + 0];
    const float py = pos[3 * i + 1];
    const float pz = pos[3 * i + 2];

    const uint64_t npx  = pk2(-px, -px);
    const uint64_t npy  = pk2(-py, -py);
    const uint64_t npz  = pk2(-pz, -pz);
    const uint64_t eps2 = pk2(1e-4f, 1e-4f);

    uint64_t FX = pk2(0.f, 0.f);
    uint64_t FY = pk2(0.f, 0.f);
    uint64_t FZ = pk2(0.f, 0.f);

    const ulonglong2* __restrict__ sXY = reinterpret_cast<const ulonglong2*>(shXY);
    const ulonglong2* __restrict__ sZM = reinterpret_cast<const ulonglong2*>(shZM);

#pragma unroll 8
    for (int p = 0; p < PAIRS; ++p) {
        const ulonglong2 xy = sXY[p];   // LDS.128: X pair + Y pair
        const ulonglong2 zm = sZM[p];   // LDS.128: Z pair + M pair

        const uint64_t dx = add2(xy.x, npx);
        const uint64_t dy = add2(xy.y, npy);
        const uint64_t dz = add2(zm.x, npz);
        const uint64_t d2 = fma2(dx, dx, fma2(dy, dy, fma2(dz, dz, eps2)));

        float d2lo, d2hi;
        upk2(d2, d2lo, d2hi);
        const uint64_t R  = pk2(rsqrtf(d2lo), rsqrtf(d2hi));  // 2x MUFU.RSQ
        const uint64_t R2 = mul2(R, R);
        const uint64_t R3 = mul2(R2, R);
        const uint64_t W  = mul2(R3, zm.y);                   // m_j * d^-1.5

        FX = fma2(W, dx, FX);
        FY = fma2(W, dy, FY);
        FZ = fma2(W, dz, FZ);
    }

    float a, b;
    upk2(FX, a, b); atomicAdd(&out[3 * i + 0], a + b);
    upk2(FY, a, b); atomicAdd(&out[3 * i + 1], a + b);
    upk2(FZ, a, b); atomicAdd(&out[3 * i + 2], a + b);
}

extern "C" void kernel_launch(void* const* d_in, const int* in_sizes, int n_in,
                              void* d_out, int out_size)
{
    const float* pos  = (const float*)d_in[0];   // [8192, 3] fp32
    const float* mass = (const float*)d_in[1];   // [8192]    fp32
    float*       out  = (float*)d_out;           // [8192, 3] fp32

    cudaMemsetAsync(out, 0, (size_t)out_size * sizeof(float));

    dim3 grid(NBODY / BLOCK, NSPLIT);            // 32 x 32 = 1024 CTAs
    nbody_kernel<<<grid, BLOCK>>>(pos, mass, out);
}

// round 9
// speedup vs baseline: 1.1187x; 1.1187x over previous
#include <cuda_runtime.h>

// N-body all-pairs gravity, fp32 scalar (packed f32x2 proven half-rate, abandoned).
// IBLK=4: each thread owns FOUR i-bodies -> one LDS.128 + loop overhead per j
// amortized over 4 interactions, and 4 independent RSQ/FMA chains per thread
// to keep issue slots full while MUFU results are pending.

constexpr int NBODY  = 8192;
constexpr int BLOCK  = 256;
constexpr int IBLK   = 4;
constexpr int ISTRIDE = NBODY / IBLK;         // 2048
constexpr int NSPLIT = 128;                   // j-dimension splits
constexpr int CHUNK  = NBODY / NSPLIT;        // 64 j-bodies per tile (1 KB)

__global__ __launch_bounds__(BLOCK)
void nbody_kernel(const float* __restrict__ pos,
                  const float* __restrict__ mass,
                  float* __restrict__ out)
{
    __shared__ float4 sh[CHUNK];

    const int i0    = blockIdx.x * BLOCK + threadIdx.x;   // [0, 2048)
    const int jBase = blockIdx.y * CHUNK;

    if (threadIdx.x < CHUNK) {
        const int j = jBase + threadIdx.x;
        sh[threadIdx.x] = make_float4(pos[3 * j + 0], pos[3 * j + 1],
                                      pos[3 * j + 2], mass[j]);
    }
    __syncthreads();

    float px[IBLK], py[IBLK], pz[IBLK];
    float fx[IBLK], fy[IBLK], fz[IBLK];
#pragma unroll
    for (int k = 0; k < IBLK; ++k) {
        const int i = i0 + k * ISTRIDE;
        px[k] = pos[3 * i + 0];
        py[k] = pos[3 * i + 1];
        pz[k] = pos[3 * i + 2];
        fx[k] = 0.f; fy[k] = 0.f; fz[k] = 0.f;
    }

#pragma unroll 8
    for (int t = 0; t < CHUNK; ++t) {
        const float4 b = sh[t];          // one LDS.128 serves 4 i-bodies
#pragma unroll
        for (int k = 0; k < IBLK; ++k) { // 4 independent chains
            const float dx = b.x - px[k];
            const float dy = b.y - py[k];
            const float dz = b.z - pz[k];
            const float d2 = fmaf(dx, dx, fmaf(dy, dy, fmaf(dz, dz, 1e-4f)));
            const float r  = rsqrtf(d2);
            const float w  = b.w * r * r * r;
            fx[k] = fmaf(w, dx, fx[k]);
            fy[k] = fmaf(w, dy, fy[k]);
            fz[k] = fmaf(w, dz, fz[k]);
        }
    }

#pragma unroll
    for (int k = 0; k < IBLK; ++k) {
        const int i = i0 + k * ISTRIDE;
        atomicAdd(&out[3 * i + 0], fx[k]);
        atomicAdd(&out[3 * i + 1], fy[k]);
        atomicAdd(&out[3 * i + 2], fz[k]);
    }
}

extern "C" void kernel_launch(void* const* d_in, const int* in_sizes, int n_in,
                              void* d_out, int out_size)
{
    const float* pos  = (const float*)d_in[0];   // [8192, 3] fp32
    const float* mass = (const float*)d_in[1];   // [8192]    fp32
    float*       out  = (float*)d_out;           // [8192, 3] fp32

    cudaMemsetAsync(out, 0, (size_t)out_size * sizeof(float));

    dim3 grid(ISTRIDE / BLOCK, NSPLIT);          // 8 x 128 = 1024 CTAs
    nbody_kernel<<<grid, BLOCK>>>(pos, mass, out);
}